// round 3
// baseline (speedup 1.0000x reference)
#include <cuda_runtime.h>
#include <math.h>
#include <stdint.h>

#define HID   100
#define NPATH 4864
#define NSEG  101
#define SSTR  148          // stage row stride (floats), mult of 4 for float4 flush

// ---------------- static device scratch (no allocation allowed) ----------------
__device__ float g_T[HID];           // sorted relu thresholds
__device__ int   g_sortIdx[HID];     // unit id per sorted threshold
__device__ float g_CG[1225];         // flattened real-CG tensors (19 tensors)
__device__ int   g_slotdesc[259];    // packed descriptors for CY slots
__device__ float g_A[NSEG*NPATH];    // per-segment linear coeff tables
__device__ float g_B[NSEG*NPATH];

// pair = lo*3 + li
__constant__ int d_NLF[9]   = {1,1,1, 1,3,3, 1,3,5};
__constant__ int d_LFMIN[9] = {0,1,2, 1,0,1, 2,1,0};
__constant__ int d_TBASE[9] = {0,1,2, 3,4,7, 10,11,14};
__constant__ int d_CGOFF[19]= {0,1,10,35,44,53,80,125,170,245,350,375,420,495,600,625,700,825,1000};
__constant__ int d_TLO[19]  = {0,0,0,1,1,1,1,1,1,1,2,2,2,2,2,2,2,2,2};
__constant__ int d_TLI[19]  = {0,1,2,0,1,1,1,2,2,2,0,1,1,1,2,2,2,2,2};
__constant__ int d_TLF[19]  = {0,1,2,1,0,1,2,1,2,3,2,1,2,3,0,1,2,3,4};

// ============== init 1: sorted thresholds + CY slot descriptors ==============
__global__ void k_init_sort(const float* __restrict__ W1, const float* __restrict__ b1){
    int t = threadIdx.x;
    __shared__ float th[HID];
    if (t < HID){
        float w = W1[t];
        th[t] = (w != 0.0f) ? (-b1[t] / w) : -1e30f;
    }
    __syncthreads();
    if (t < HID){
        float mine = th[t];
        int rank = 0;
        for (int i = 0; i < HID; i++){
            float o = th[i];
            rank += (o < mine) || (o == mine && i < t);
        }
        g_T[rank] = mine;
        g_sortIdx[rank] = t;
    }
    if (t == 0){
        int s = 0;
        for (int pair = 0; pair < 9; pair++){
            int lo = pair / 3, li = pair % 3;
            int da = 2*lo+1, db = 2*li+1;
            int nlf = d_NLF[pair], lfmin = d_LFMIN[pair];
            for (int a = 0; a < da; a++)
                for (int k = 0; k < nlf; k++)
                    for (int b = 0; b < db; b++){
                        int lf = lfmin + k;
                        int cgbase = d_CGOFF[d_TBASE[pair]+k] + (a*db + b)*(2*lf+1);
                        g_slotdesc[s++] = cgbase | ((lf*lf) << 12) | ((2*lf+1) << 17) | (pair << 22);
                    }
        }
    }
}

// ============== init 2: real Clebsch-Gordan tensors (fp64, exact ref mirror) ==============
__device__ __forceinline__ double dfact(int n){
    double f = 1.0;
    for (int i = 2; i <= n; i++) f *= (double)i;
    return f;
}
__device__ double cgval(int j1,int j2,int j3,int m1,int m2){
    int m3 = m1 + m2;
    if (abs(m3) > j3) return 0.0;
    double pref0 = sqrt((double)(2*j3+1) * dfact(j1+j2-j3) * dfact(j1-j2+j3) *
                        dfact(-j1+j2+j3) / dfact(j1+j2+j3+1));
    double pref = pref0 * sqrt(dfact(j3+m3)*dfact(j3-m3)*dfact(j1-m1)*dfact(j1+m1)*
                               dfact(j2-m2)*dfact(j2+m2));
    int klo = max(0, max(j2-j3-m1, j1+m2-j3));
    int khi = min(j1+j2-j3, min(j1-m1, j2+m2));
    double s = 0.0;
    for (int k = klo; k <= khi; k++){
        double d = dfact(k)*dfact(j1+j2-j3-k)*dfact(j1-m1-k)*dfact(j2+m2-k)*
                   dfact(j3-j2+m1+k)*dfact(j3-j1-m2+k);
        s += ((k & 1) ? -1.0 : 1.0) / d;
    }
    return pref * s;
}
__device__ double w3j_entry(int j1,int j2,int j3,int mi,int ni,int ki){
    int m1 = mi - j1, m2 = ni - j2, m3 = ki - j3;
    if (m1 + m2 + m3 != 0) return 0.0;
    double cg = cgval(j1, j2, j3, m1, m2);
    int e = j1 - j2 + m3;
    double sgn = (e & 1) ? -1.0 : 1.0;
    return sgn * cg / sqrt((double)(2*j3+1));
}
__device__ __forceinline__ void qvalc(int l, int i, int j, double& re, double& im){
    re = 0.0; im = 0.0;
    const double s2 = 0.7071067811865476;
    int m = i - l;
    if (m == 0){ if (j == l) re = 1.0; return; }
    if (m > 0){
        if (j == l+m)      re = (m & 1) ? -s2 : s2;
        else if (j == l-m) re = s2;
    } else {
        int mm = -m;
        if (j == l-mm)      im = s2;
        else if (j == l+mm) im = (mm & 1) ? s2 : -s2;
    }
}
__device__ __forceinline__ int qcols(int l, int row, int* s){
    if (row == l){ s[0] = l; return 1; }
    s[0] = row; s[1] = 2*l - row; return 2;
}
__global__ void k_init_cg(){
    int tens = blockIdx.x;
    int lo = d_TLO[tens], li = d_TLI[tens], lf = d_TLF[tens];
    int da = 2*lo+1, db = 2*li+1, dc = 2*lf+1;
    int n = da*db*dc;
    __shared__ double sre[225], sim2[225];
    __shared__ double s_nr, s_ni;
    for (int e = threadIdx.x; e < n; e += blockDim.x){
        int cc = e % dc; int ab = e / dc; int b = ab % db; int a = ab / db;
        int mset[2], nset[2], kset[2];
        int nm = qcols(lo, a, mset);
        int nn = qcols(li, b, nset);
        int nk = qcols(lf, cc, kset);
        double re = 0.0, imv = 0.0;
        for (int i1 = 0; i1 < nm; i1++){
            double q1r, q1i; qvalc(lo, a, mset[i1], q1r, q1i);
            for (int i2 = 0; i2 < nn; i2++){
                double q2r, q2i; qvalc(li, b, nset[i2], q2r, q2i);
                double q12r = q1r*q2r - q1i*q2i;
                double q12i = q1r*q2i + q1i*q2r;
                for (int i3 = 0; i3 < nk; i3++){
                    double q3r, q3i; qvalc(lf, cc, kset[i3], q3r, q3i);
                    double w = w3j_entry(lo, li, lf, mset[i1], nset[i2], kset[i3]);
                    if (w != 0.0){
                        re  += (q12r*q3r - q12i*q3i) * w;
                        imv += (q12r*q3i + q12i*q3r) * w;
                    }
                }
            }
        }
        sre[e] = re; sim2[e] = imv;
    }
    __syncthreads();
    if (threadIdx.x == 0){
        double nr = 0.0, ni = 0.0;
        for (int e = 0; e < n; e++){ nr += sre[e]*sre[e]; ni += sim2[e]*sim2[e]; }
        s_nr = nr; s_ni = ni;
    }
    __syncthreads();
    bool use_re = (s_nr >= s_ni);
    double inv = 1.0 / sqrt(use_re ? s_nr : s_ni);
    int base = d_CGOFF[tens];
    for (int e = threadIdx.x; e < n; e += blockDim.x)
        g_CG[base + e] = (float)((use_re ? sre[e] : sim2[e]) * inv);
}

// ============== init 3: piecewise-linear coeff tables ==============
__global__ void k_init_ab(const float* __restrict__ W1, const float* __restrict__ b1,
                          const float* __restrict__ W2){
    int p = blockIdx.x * blockDim.x + threadIdx.x;
    if (p >= NPATH) return;
    float A = 0.f, Bv = 0.f;
    // base segment (radius below all thresholds): w<0 active; w==0 active iff b>0
    for (int t = 0; t < HID; t++){
        float w = W1[t], bb = b1[t];
        bool act = (w < 0.0f) || (w == 0.0f && bb > 0.0f);
        if (act){
            float w2 = W2[t*NPATH + p];
            A  = fmaf(w,  w2, A);
            Bv = fmaf(bb, w2, Bv);
        }
    }
    g_A[p] = A; g_B[p] = Bv;
    for (int s = 1; s < NSEG; s++){
        int u  = g_sortIdx[s-1];
        float w = W1[u], bb = b1[u];
        float w2 = W2[u*NPATH + p];
        float sg = (w > 0.0f) ? 1.0f : ((w < 0.0f) ? -1.0f : 0.0f);
        A  = fmaf(sg*w,  w2, A);
        Bv = fmaf(sg*bb, w2, Bv);
        g_A[s*NPATH + p] = A;
        g_B[s*NPATH + p] = Bv;
    }
}

// ============== main kernel: one CTA per point ==============
template<int NLF, int DB>
__device__ __forceinline__ void do_block(const float* __restrict__ cyp,
                                         const float* __restrict__ cf_base,
                                         float* __restrict__ stg){
    float cy[NLF*DB];
    #pragma unroll
    for (int t = 0; t < NLF*DB; t++) cy[t] = cyp[t];
    #pragma unroll 4
    for (int v = 0; v < 16; v++){
        float cf[NLF];
        #pragma unroll
        for (int k = 0; k < NLF; k++) cf[k] = cf_base[v*NLF + k];
        #pragma unroll
        for (int j = 0; j < DB; j++){
            float acc = 0.f;
            #pragma unroll
            for (int k = 0; k < NLF; k++) acc = fmaf(cy[k*DB+j], cf[k], acc);
            stg[v*DB + j] = acc;
        }
    }
}

extern __shared__ float smem[];

__global__ __launch_bounds__(256, 2)
void k_main(const float* __restrict__ r, float* __restrict__ out){
    float* sStage = smem;                 // 144*SSTR floats (offset 0 -> 16B aligned)
    float* sC     = smem + 144*SSTR;      // 4864
    float* sY     = sC + NPATH;           // 32
    float* sCY    = sY + 32;              // 259

    int z   = blockIdx.x;
    int tid = threadIdx.x;

    // --- point data (all threads; r loads broadcast) ---
    float x = r[3*z+0], y = r[3*z+1], zz = r[3*z+2];
    float rad = sqrtf(x*x + y*y + zz*zz);
    bool  iszero = (rad == 0.0f);
    float inv = 1.0f / fmaxf(rad, 1e-12f);
    float ux = x*inv, uy = y*inv, uz = zz*inv;

    if (tid == 0){
        float X = ux, Y = uy, Z = uz;
        float X2 = X*X, Y2 = Y*Y, Z2 = Z*Z;
        sY[0]  = 0.28209479177387814f;
        sY[1]  = 0.4886025119029199f * Y;
        sY[2]  = 0.4886025119029199f * Z;
        sY[3]  = 0.4886025119029199f * X;
        sY[4]  = 1.0925484305920792f * X*Y;
        sY[5]  = 1.0925484305920792f * Y*Z;
        sY[6]  = 0.31539156525252005f * (3.f*Z2 - 1.f);
        sY[7]  = 1.0925484305920792f * X*Z;
        sY[8]  = 0.5462742152960396f * (X2 - Y2);
        sY[9]  = 0.5900435899266435f * Y*(3.f*X2 - Y2);
        sY[10] = 2.890611442640554f  * X*Y*Z;
        sY[11] = 0.4570457994644658f * Y*(5.f*Z2 - 1.f);
        sY[12] = 0.3731763325901154f * Z*(5.f*Z2 - 3.f);
        sY[13] = 0.4570457994644658f * X*(5.f*Z2 - 1.f);
        sY[14] = 1.445305721320277f  * (X2 - Y2)*Z;        // 0.25*sqrt(105/pi)
        sY[15] = 0.5900435899266435f * X*(X2 - 3.f*Y2);
        sY[16] = 2.5033429417967046f * X*Y*(X2 - Y2);
        sY[17] = 1.7701307697799304f * Y*(3.f*X2 - Y2)*Z;
        sY[18] = 0.9461746957575601f * X*Y*(7.f*Z2 - 1.f);
        sY[19] = 0.6690465435572892f * Y*Z*(7.f*Z2 - 3.f);
        sY[20] = 0.10578554691520431f * (35.f*Z2*Z2 - 30.f*Z2 + 3.f);
        sY[21] = 0.6690465435572892f * X*Z*(7.f*Z2 - 3.f);
        sY[22] = 0.47308734787878004f * (X2 - Y2)*(7.f*Z2 - 1.f);
        sY[23] = 1.7701307697799304f * X*(X2 - 3.f*Y2)*Z;
        sY[24] = 0.6258357354491761f * (X2*X2 - 6.f*X2*Y2 + Y2*Y2);
    }

    bool pred = (tid < HID) && (g_T[tid] < rad);
    int seg = __syncthreads_count(pred);   // also barrier: sY now visible

    // --- coeff: piecewise-linear eval from L2-resident tables ---
    {
        const float* Ab = g_A + (size_t)seg * NPATH;
        const float* Bb = g_B + (size_t)seg * NPATH;
        #pragma unroll
        for (int it = 0; it < NPATH/256; it++){
            int p = it*256 + tid;
            sC[p] = fmaf(rad, Ab[p], Bb[p]);
        }
    }

    // --- CY = norm * (C . Y), 259 slots ---
    for (int s = tid; s < 259; s += 256){
        int desc = g_slotdesc[s];
        int cgbase = desc & 0xFFF;
        int yoff   = (desc >> 12) & 0x1F;
        int dc     = (desc >> 17) & 0x1F;
        int pair   = desc >> 22;
        int lo = pair / 3, li = pair - lo*3;
        float v = 0.f;
        for (int m = 0; m < dc; m++)
            v = fmaf(g_CG[cgbase + m], sY[yoff + m], v);
        float lm = sqrtf((float)(2*li+1) * 12.566370614359172f);
        float num = (lo == 0) ? 48.f : ((lo == 1) ? 112.f : 144.f);
        float nrm = iszero ? (lm * 0.25f) : (lm * rsqrtf(num));
        sCY[s] = v * nrm;
    }
    __syncthreads();

    // --- 144 row threads compute one output row each into padded stage ---
    if (tid < 144){
        int lo, u, i;
        if (tid < 16){ lo = 0; u = tid; i = 0; }
        else if (tid < 64){ int t = tid - 16; lo = 1; u = t/3; i = t - u*3; }
        else { int t = tid - 64; lo = 2; u = t/5; i = t - u*5; }
        float* stg = sStage + tid * SSTR;
        if (lo == 0){
            do_block<1,1>(sCY + 0 + i*1,  sC + 0    + u*16, stg + 0);
            do_block<1,3>(sCY + 1 + i*3,  sC + 256  + u*16, stg + 16);
            do_block<1,5>(sCY + 4 + i*5,  sC + 512  + u*16, stg + 64);
        } else if (lo == 1){
            do_block<1,1>(sCY + 9  + i*1,  sC + 768  + u*16, stg + 0);
            do_block<3,3>(sCY + 12 + i*9,  sC + 1024 + u*48, stg + 16);
            do_block<3,5>(sCY + 39 + i*15, sC + 1792 + u*48, stg + 64);
        } else {
            do_block<1,1>(sCY + 84  + i*1,  sC + 2560 + u*16, stg + 0);
            do_block<3,3>(sCY + 89  + i*9,  sC + 2816 + u*48, stg + 16);
            do_block<5,5>(sCY + 134 + i*25, sC + 3584 + u*80, stg + 64);
        }
    }
    __syncthreads();

    // --- coalesced float4 flush: 144*144 = 5184 float4 ---
    float4* outz = (float4*)(out + (size_t)z * 20736);
    for (int q = tid; q < 5184; q += 256){
        int row = q / 36;               // 36 float4 per row
        int c4  = q - row*36;
        outz[q] = *(const float4*)(sStage + row*SSTR + c4*4);
    }
}

extern "C" void kernel_launch(void* const* d_in, const int* in_sizes, int n_in,
                              void* d_out, int out_size){
    const float* r  = (const float*)d_in[0];
    const float* W1 = (const float*)d_in[1];
    const float* b1 = (const float*)d_in[2];
    const float* W2 = (const float*)d_in[3];
    float* out = (float*)d_out;

    static bool attr_set = false;
    int smem_bytes = (144*SSTR + NPATH + 32 + 260) * 4;
    if (!attr_set){
        cudaFuncSetAttribute(k_main, cudaFuncAttributeMaxDynamicSharedMemorySize, smem_bytes);
        attr_set = true;
    }

    k_init_sort<<<1, 128>>>(W1, b1);
    k_init_cg<<<19, 128>>>();
    k_init_ab<<<(NPATH + 255)/256, 256>>>(W1, b1, W2);
    k_main<<<8192, 256, smem_bytes>>>(r, out);
}

// round 4
// speedup vs baseline: 1.3128x; 1.3128x over previous
#include <cuda_runtime.h>
#include <math.h>
#include <stdint.h>

#define HID   100
#define NPATH 4864
#define NSEG  101
#define SSTR  148          // stage row stride in floats = 37 float4 (odd -> conflict-free STS.128)

// ---------------- static device scratch (no allocation allowed) ----------------
__device__ float g_T[HID];            // sorted relu thresholds
__device__ int   g_sortIdx[HID];      // unit id per sorted threshold
__device__ int   g_rank[HID];         // rank per unit id
__device__ float g_CG[1225];          // flattened real-CG tensors (19 tensors)
__device__ int   g_slotdesc[259];     // packed descriptors for CY slots
__device__ __align__(16) float g_A[NSEG*NPATH];   // per-segment linear tables (PERMUTED layout)
__device__ __align__(16) float g_B[NSEG*NPATH];

// pair = lo*3 + li
__constant__ int d_NLF[9]   = {1,1,1, 1,3,3, 1,3,5};
__constant__ int d_LFMIN[9] = {0,1,2, 1,0,1, 2,1,0};
__constant__ int d_TBASE[9] = {0,1,2, 3,4,7, 10,11,14};
__constant__ int d_CGOFF[19]= {0,1,10,35,44,53,80,125,170,245,350,375,420,495,600,625,700,825,1000};
__constant__ int d_TLO[19]  = {0,0,0,1,1,1,1,1,1,1,2,2,2,2,2,2,2,2,2};
__constant__ int d_TLI[19]  = {0,1,2,0,1,1,1,2,2,2,0,1,1,1,2,2,2,2,2};
__constant__ int d_TLF[19]  = {0,1,2,1,0,1,2,1,2,3,2,1,2,3,0,1,2,3,4};

// path index permutation: (u*16+v)*nlf+k  ->  (v*nlf+k)*16+u  (u innermost)
__device__ __forceinline__ int permute_path(int p){
    int base, nlf;
    if      (p < 256)  { base = 0;    nlf = 1; }
    else if (p < 512)  { base = 256;  nlf = 1; }
    else if (p < 768)  { base = 512;  nlf = 1; }
    else if (p < 1024) { base = 768;  nlf = 1; }
    else if (p < 1792) { base = 1024; nlf = 3; }
    else if (p < 2560) { base = 1792; nlf = 3; }
    else if (p < 2816) { base = 2560; nlf = 1; }
    else if (p < 3584) { base = 2816; nlf = 3; }
    else               { base = 3584; nlf = 5; }
    int local = p - base;
    int u   = local / (16*nlf);
    int rem = local - u*16*nlf;
    return base + rem*16 + u;
}

// ============== init 1: sorted thresholds + ranks + CY slot descriptors ==============
__global__ void k_init_sort(const float* __restrict__ W1, const float* __restrict__ b1){
    int t = threadIdx.x;
    __shared__ float th[HID];
    if (t < HID){
        float w = W1[t];
        th[t] = (w != 0.0f) ? (-b1[t] / w) : -1e30f;
    }
    __syncthreads();
    if (t < HID){
        float mine = th[t];
        int rank = 0;
        for (int i = 0; i < HID; i++){
            float o = th[i];
            rank += (o < mine) || (o == mine && i < t);
        }
        g_T[rank] = mine;
        g_sortIdx[rank] = t;
        g_rank[t] = rank;
    }
    if (t == 0){
        int s = 0;
        for (int pair = 0; pair < 9; pair++){
            int lo = pair / 3, li = pair % 3;
            int da = 2*lo+1, db = 2*li+1;
            int nlf = d_NLF[pair], lfmin = d_LFMIN[pair];
            for (int a = 0; a < da; a++)
                for (int k = 0; k < nlf; k++)
                    for (int b = 0; b < db; b++){
                        int lf = lfmin + k;
                        int cgbase = d_CGOFF[d_TBASE[pair]+k] + (a*db + b)*(2*lf+1);
                        g_slotdesc[s++] = cgbase | ((lf*lf) << 12) | ((2*lf+1) << 17) | (pair << 22);
                    }
        }
    }
}

// ============== init 2: real Clebsch-Gordan tensors (fp64, exact ref mirror) ==============
__device__ double cgval(int j1,int j2,int j3,int m1,int m2, const double* __restrict__ F, double pref0){
    int m3 = m1 + m2;
    if (abs(m3) > j3) return 0.0;
    double pref = pref0 * sqrt(F[j3+m3]*F[j3-m3]*F[j1-m1]*F[j1+m1]*F[j2-m2]*F[j2+m2]);
    int klo = max(0, max(j2-j3-m1, j1+m2-j3));
    int khi = min(j1+j2-j3, min(j1-m1, j2+m2));
    double s = 0.0;
    for (int k = klo; k <= khi; k++){
        double d = F[k]*F[j1+j2-j3-k]*F[j1-m1-k]*F[j2+m2-k]*F[j3-j2+m1+k]*F[j3-j1-m2+k];
        s += ((k & 1) ? -1.0 : 1.0) / d;
    }
    return pref * s;
}
__device__ __forceinline__ double w3j_entry(int j1,int j2,int j3,int mi,int ni,int ki,
                                            const double* __restrict__ F, double pref0, double inv2j3){
    int m1 = mi - j1, m2 = ni - j2, m3 = ki - j3;
    if (m1 + m2 + m3 != 0) return 0.0;
    double cg = cgval(j1, j2, j3, m1, m2, F, pref0);
    int e = j1 - j2 + m3;
    double sgn = (e & 1) ? -1.0 : 1.0;
    return sgn * cg * inv2j3;
}
__device__ __forceinline__ void qvalc(int l, int i, int j, double& re, double& im){
    re = 0.0; im = 0.0;
    const double s2 = 0.7071067811865476;
    int m = i - l;
    if (m == 0){ if (j == l) re = 1.0; return; }
    if (m > 0){
        if (j == l+m)      re = (m & 1) ? -s2 : s2;
        else if (j == l-m) re = s2;
    } else {
        int mm = -m;
        if (j == l-mm)      im = s2;
        else if (j == l+mm) im = (mm & 1) ? s2 : -s2;
    }
}
__device__ __forceinline__ int qcols(int l, int row, int* s){
    if (row == l){ s[0] = l; return 1; }
    s[0] = row; s[1] = 2*l - row; return 2;
}
__global__ void k_init_cg(){
    int tens = blockIdx.x;
    int lo = d_TLO[tens], li = d_TLI[tens], lf = d_TLF[tens];
    int da = 2*lo+1, db = 2*li+1, dc = 2*lf+1;
    int n = da*db*dc;
    __shared__ double sre[225], sim2[225];
    __shared__ double sF[12];
    __shared__ double s_pref0, s_inv2j3, s_nr, s_ni;
    if (threadIdx.x == 0){
        double f = 1.0;
        sF[0] = 1.0;
        for (int i = 1; i < 12; i++){ f *= (double)i; sF[i] = f; }
        s_pref0 = sqrt((double)(2*lf+1) * sF[lo+li-lf+ (lf>lo+li?0:0)] * 0.0 + 0.0); // placeholder (recomputed below)
        s_pref0 = sqrt((double)(2*lf+1) * sF[lo+li-lf] * sF[lo-li+lf] * sF[-lo+li+lf] / sF[lo+li+lf+1]);
        s_inv2j3 = 1.0 / sqrt((double)(2*lf+1));
    }
    __syncthreads();
    const double* F = sF;
    for (int e = threadIdx.x; e < n; e += blockDim.x){
        int cc = e % dc; int ab = e / dc; int b = ab % db; int a = ab / db;
        int mset[2], nset[2], kset[2];
        int nm = qcols(lo, a, mset);
        int nn = qcols(li, b, nset);
        int nk = qcols(lf, cc, kset);
        double re = 0.0, imv = 0.0;
        for (int i1 = 0; i1 < nm; i1++){
            double q1r, q1i; qvalc(lo, a, mset[i1], q1r, q1i);
            for (int i2 = 0; i2 < nn; i2++){
                double q2r, q2i; qvalc(li, b, nset[i2], q2r, q2i);
                double q12r = q1r*q2r - q1i*q2i;
                double q12i = q1r*q2i + q1i*q2r;
                for (int i3 = 0; i3 < nk; i3++){
                    double q3r, q3i; qvalc(lf, cc, kset[i3], q3r, q3i);
                    double w = w3j_entry(lo, li, lf, mset[i1], nset[i2], kset[i3], F, s_pref0, s_inv2j3);
                    if (w != 0.0){
                        re  += (q12r*q3r - q12i*q3i) * w;
                        imv += (q12r*q3i + q12i*q3r) * w;
                    }
                }
            }
        }
        sre[e] = re; sim2[e] = imv;
    }
    __syncthreads();
    if (threadIdx.x == 0){
        double nr = 0.0, ni = 0.0;
        for (int e = 0; e < n; e++){ nr += sre[e]*sre[e]; ni += sim2[e]*sim2[e]; }
        s_nr = nr; s_ni = ni;
    }
    __syncthreads();
    bool use_re = (s_nr >= s_ni);
    double inv = 1.0 / sqrt(use_re ? s_nr : s_ni);
    int base = d_CGOFF[tens];
    for (int e = threadIdx.x; e < n; e += blockDim.x)
        g_CG[base + e] = (float)((use_re ? sre[e] : sim2[e]) * inv);
}

// ============== init 3: piecewise-linear coeff tables (parallel over seg chunks) ==============
// segment s = #{thresholds < rad}. Unit active: w>0 -> rank < s ; w<0 -> rank >= s ; w==0 -> b>0.
__global__ void k_init_ab(const float* __restrict__ W1, const float* __restrict__ b1,
                          const float* __restrict__ W2){
    int p  = blockIdx.x * 256 + threadIdx.x;
    int s0 = blockIdx.y * 4;
    if (p >= NPATH) return;
    int pn = permute_path(p);

    float A = 0.f, Bv = 0.f;
    for (int t = 0; t < HID; t++){
        float w = W1[t], bb = b1[t];
        int rk = g_rank[t];
        bool act = (w > 0.0f) ? (rk < s0) : ((w < 0.0f) ? (rk >= s0) : (bb > 0.0f));
        if (act){                               // warp-uniform branch
            float w2 = W2[t*NPATH + p];
            A  = fmaf(w,  w2, A);
            Bv = fmaf(bb, w2, Bv);
        }
    }
    g_A[s0*NPATH + pn] = A;
    g_B[s0*NPATH + pn] = Bv;
    #pragma unroll
    for (int d = 1; d < 4; d++){
        int s = s0 + d;
        if (s >= NSEG) break;
        int u  = g_sortIdx[s-1];
        float w = W1[u], bb = b1[u];
        float w2 = W2[u*NPATH + p];
        float sg = (w > 0.0f) ? 1.0f : ((w < 0.0f) ? -1.0f : 0.0f);
        A  = fmaf(sg*w,  w2, A);
        Bv = fmaf(sg*bb, w2, Bv);
        g_A[s*NPATH + pn] = A;
        g_B[s*NPATH + pn] = Bv;
    }
}

// ============== main kernel: one CTA per point ==============
// coeff smem layout per pair block: idx = (v*nlf + k)*16 + u  (u innermost -> conflict-free LDS)
template<int NLF, int DB>
__device__ __forceinline__ void do_block(const float* __restrict__ cy_s,
                                         const float* __restrict__ cf_u,   // sC + pbase + u
                                         float* __restrict__ stg){         // row base + col base
    float cy[NLF*DB];
    #pragma unroll
    for (int t = 0; t < NLF*DB; t++) cy[t] = cy_s[t];
    float fb0, fb1, fb2;
    #pragma unroll
    for (int v = 0; v < 16; v++){
        float cf[NLF];
        #pragma unroll
        for (int k = 0; k < NLF; k++) cf[k] = cf_u[(v*NLF + k)*16];
        #pragma unroll
        for (int j = 0; j < DB; j++){
            float acc = 0.f;
            #pragma unroll
            for (int k = 0; k < NLF; k++) acc = fmaf(cy[k*DB + j], cf[k], acc);
            int col = v*DB + j;                   // compile-time (full unroll)
            int ph  = col & 3;
            if      (ph == 0) fb0 = acc;
            else if (ph == 1) fb1 = acc;
            else if (ph == 2) fb2 = acc;
            else *(float4*)(stg + (col - 3)) = make_float4(fb0, fb1, fb2, acc);
        }
    }
}

extern __shared__ float smem[];

__global__ __launch_bounds__(256, 2)
void k_main(const float* __restrict__ r, float* __restrict__ out){
    float* sStage = smem;                 // 144*SSTR floats, 16B aligned
    float* sC     = smem + 144*SSTR;      // 4864 (16B aligned: 144*148*4 % 16 == 0)
    float* sY     = sC + NPATH;           // 32
    float* sCY    = sY + 32;              // 259

    int z   = blockIdx.x;
    int tid = threadIdx.x;

    float x = r[3*z+0], y = r[3*z+1], zz = r[3*z+2];
    float rad = sqrtf(x*x + y*y + zz*zz);
    bool  iszero = (rad == 0.0f);
    float inv = 1.0f / fmaxf(rad, 1e-12f);
    float ux = x*inv, uy = y*inv, uz = zz*inv;

    if (tid == 0){
        float X = ux, Y = uy, Z = uz;
        float X2 = X*X, Y2 = Y*Y, Z2 = Z*Z;
        sY[0]  = 0.28209479177387814f;
        sY[1]  = 0.4886025119029199f * Y;
        sY[2]  = 0.4886025119029199f * Z;
        sY[3]  = 0.4886025119029199f * X;
        sY[4]  = 1.0925484305920792f * X*Y;
        sY[5]  = 1.0925484305920792f * Y*Z;
        sY[6]  = 0.31539156525252005f * (3.f*Z2 - 1.f);
        sY[7]  = 1.0925484305920792f * X*Z;
        sY[8]  = 0.5462742152960396f * (X2 - Y2);
        sY[9]  = 0.5900435899266435f * Y*(3.f*X2 - Y2);
        sY[10] = 2.890611442640554f  * X*Y*Z;
        sY[11] = 0.4570457994644658f * Y*(5.f*Z2 - 1.f);
        sY[12] = 0.3731763325901154f * Z*(5.f*Z2 - 3.f);
        sY[13] = 0.4570457994644658f * X*(5.f*Z2 - 1.f);
        sY[14] = 1.445305721320277f  * (X2 - Y2)*Z;
        sY[15] = 0.5900435899266435f * X*(X2 - 3.f*Y2);
        sY[16] = 2.5033429417967046f * X*Y*(X2 - Y2);
        sY[17] = 1.7701307697799304f * Y*(3.f*X2 - Y2)*Z;
        sY[18] = 0.9461746957575601f * X*Y*(7.f*Z2 - 1.f);
        sY[19] = 0.6690465435572892f * Y*Z*(7.f*Z2 - 3.f);
        sY[20] = 0.10578554691520431f * (35.f*Z2*Z2 - 30.f*Z2 + 3.f);
        sY[21] = 0.6690465435572892f * X*Z*(7.f*Z2 - 3.f);
        sY[22] = 0.47308734787878004f * (X2 - Y2)*(7.f*Z2 - 1.f);
        sY[23] = 1.7701307697799304f * X*(X2 - 3.f*Y2)*Z;
        sY[24] = 0.6258357354491761f * (X2*X2 - 6.f*X2*Y2 + Y2*Y2);
    }

    bool pred = (tid < HID) && (g_T[tid] < rad);
    int seg = __syncthreads_count(pred);   // also a barrier: sY now visible

    // --- coeff: piecewise-linear eval, float4, permuted layout ---
    {
        const float4* A4 = (const float4*)(g_A + (size_t)seg * NPATH);
        const float4* B4 = (const float4*)(g_B + (size_t)seg * NPATH);
        float4* sC4 = (float4*)sC;
        #pragma unroll
        for (int it = 0; it < 5; it++){
            int idx = it*256 + tid;
            if (idx < NPATH/4){
                float4 a = __ldg(&A4[idx]);
                float4 b = __ldg(&B4[idx]);
                sC4[idx] = make_float4(fmaf(rad,a.x,b.x), fmaf(rad,a.y,b.y),
                                       fmaf(rad,a.z,b.z), fmaf(rad,a.w,b.w));
            }
        }
    }

    // --- CY = norm * (C . Y), 259 slots ---
    for (int s = tid; s < 259; s += 256){
        int desc = g_slotdesc[s];
        int cgbase = desc & 0xFFF;
        int yoff   = (desc >> 12) & 0x1F;
        int dc     = (desc >> 17) & 0x1F;
        int pair   = desc >> 22;
        int lo = pair / 3, li = pair - lo*3;
        float v = 0.f;
        for (int m = 0; m < dc; m++)
            v = fmaf(g_CG[cgbase + m], sY[yoff + m], v);
        float lm = sqrtf((float)(2*li+1) * 12.566370614359172f);
        float num = (lo == 0) ? 48.f : ((lo == 1) ? 112.f : 144.f);
        float nrm = iszero ? (lm * 0.25f) : (lm * rsqrtf(num));
        sCY[s] = v * nrm;
    }
    __syncthreads();

    // --- 144 row threads: one output row each, float4 staged, conflict-free ---
    if (tid < 144){
        int lo, u, i;
        if (tid < 16){ lo = 0; u = tid; i = 0; }
        else if (tid < 64){ int t = tid - 16; lo = 1; u = t/3; i = t - u*3; }
        else { int t = tid - 64; lo = 2; u = t/5; i = t - u*5; }
        float* stg = sStage + tid * SSTR;
        if (lo == 0){
            do_block<1,1>(sCY + 0 + i*1,  sC + 0    + u, stg + 0);
            do_block<1,3>(sCY + 1 + i*3,  sC + 256  + u, stg + 16);
            do_block<1,5>(sCY + 4 + i*5,  sC + 512  + u, stg + 64);
        } else if (lo == 1){
            do_block<1,1>(sCY + 9  + i*1,  sC + 768  + u, stg + 0);
            do_block<3,3>(sCY + 12 + i*9,  sC + 1024 + u, stg + 16);
            do_block<3,5>(sCY + 39 + i*15, sC + 1792 + u, stg + 64);
        } else {
            do_block<1,1>(sCY + 84  + i*1,  sC + 2560 + u, stg + 0);
            do_block<3,3>(sCY + 89  + i*9,  sC + 2816 + u, stg + 16);
            do_block<5,5>(sCY + 134 + i*25, sC + 3584 + u, stg + 64);
        }
    }
    __syncthreads();

    // --- coalesced float4 streaming flush: 144*36 = 5184 float4 ---
    float4* outz = (float4*)(out + (size_t)z * 20736);
    for (int q = tid; q < 5184; q += 256){
        int row = q / 36;
        int c4  = q - row*36;
        float4 vv = *(const float4*)(sStage + row*SSTR + c4*4);
        __stcs(&outz[q], vv);
    }
}

extern "C" void kernel_launch(void* const* d_in, const int* in_sizes, int n_in,
                              void* d_out, int out_size){
    const float* r  = (const float*)d_in[0];
    const float* W1 = (const float*)d_in[1];
    const float* b1 = (const float*)d_in[2];
    const float* W2 = (const float*)d_in[3];
    float* out = (float*)d_out;

    static bool attr_set = false;
    int smem_bytes = (144*SSTR + NPATH + 32 + 260) * 4;
    if (!attr_set){
        cudaFuncSetAttribute(k_main, cudaFuncAttributeMaxDynamicSharedMemorySize, smem_bytes);
        attr_set = true;
    }

    k_init_sort<<<1, 128>>>(W1, b1);
    k_init_cg<<<19, 128>>>();
    dim3 abgrid((NPATH + 255)/256, (NSEG + 3)/4);
    k_init_ab<<<abgrid, 256>>>(W1, b1, W2);
    k_main<<<8192, 256, smem_bytes>>>(r, out);
}

// round 8
// speedup vs baseline: 1.5887x; 1.2101x over previous
#include <cuda_runtime.h>
#include <math.h>
#include <stdint.h>

#define HID     100
#define NPATH   4864
#define NPAD    5168          // padded coeff table (stride 17 per u-group)
#define NSEG    101
#define SPAD    65            // private stage row stride (odd -> conflict-free banks)
#define ABCHUNK 16

// ---------------- static device scratch ----------------
__device__ float g_T[HID];
__device__ int   g_sortIdx[HID];
__device__ int   g_rank[HID];
__device__ float g_CG[1225];
__device__ int   g_slotdesc[259];
__device__ __align__(16) float g_A[NSEG*NPAD];
__device__ __align__(16) float g_B[NSEG*NPAD];

__constant__ int d_NLF[9]   = {1,1,1, 1,3,3, 1,3,5};
__constant__ int d_TBASE[9] = {0,1,2, 3,4,7, 10,11,14};
__constant__ int d_CGOFF[19]= {0,1,10,35,44,53,80,125,170,245,350,375,420,495,600,625,700,825,1000};
__constant__ int d_TLO[19]  = {0,0,0,1,1,1,1,1,1,1,2,2,2,2,2,2,2,2,2};
__constant__ int d_TLI[19]  = {0,1,2,0,1,1,1,2,2,2,0,1,1,1,2,2,2,2,2};
__constant__ int d_TLF[19]  = {0,1,2,1,0,1,2,1,2,3,2,1,2,3,0,1,2,3,4};

// original path index -> padded-permuted index: (v*nlf+k)*17 + u
__device__ __forceinline__ int permute_pad(int p){
    int base, nlf, pb17;
    if      (p < 256)  { base = 0;    nlf = 1; pb17 = 0;    }
    else if (p < 512)  { base = 256;  nlf = 1; pb17 = 272;  }
    else if (p < 768)  { base = 512;  nlf = 1; pb17 = 544;  }
    else if (p < 1024) { base = 768;  nlf = 1; pb17 = 816;  }
    else if (p < 1792) { base = 1024; nlf = 3; pb17 = 1088; }
    else if (p < 2560) { base = 1792; nlf = 3; pb17 = 1904; }
    else if (p < 2816) { base = 2560; nlf = 1; pb17 = 2720; }
    else if (p < 3584) { base = 2816; nlf = 3; pb17 = 2992; }
    else               { base = 3584; nlf = 5; pb17 = 3808; }
    int local = p - base;
    int u   = local / (16*nlf);
    int rem = local - u*16*nlf;
    return pb17 + rem*17 + u;
}

// ============== init 1 ==============
__global__ void k_init_sort(const float* __restrict__ W1, const float* __restrict__ b1){
    int t = threadIdx.x;
    __shared__ float th[HID];
    if (t < HID){
        float w = W1[t];
        th[t] = (w != 0.0f) ? (-b1[t] / w) : -1e30f;
    }
    __syncthreads();
    if (t < HID){
        float mine = th[t];
        int rank = 0;
        for (int i = 0; i < HID; i++){
            float o = th[i];
            rank += (o < mine) || (o == mine && i < t);
        }
        g_T[rank] = mine;
        g_sortIdx[rank] = t;
        g_rank[t] = rank;
    }
    if (t == 0){
        int s = 0;
        for (int pair = 0; pair < 9; pair++){
            int lo = pair / 3, li = pair % 3;
            int da = 2*lo+1, db = 2*li+1;
            int nlf = d_NLF[pair];
            int lfmin = (lo > li) ? lo - li : li - lo;
            for (int a = 0; a < da; a++)
                for (int k = 0; k < nlf; k++)
                    for (int b = 0; b < db; b++){
                        int lf = lfmin + k;
                        int cgbase = d_CGOFF[d_TBASE[pair]+k] + (a*db + b)*(2*lf+1);
                        g_slotdesc[s++] = cgbase | ((lf*lf) << 12) | ((2*lf+1) << 17) | (pair << 22);
                    }
        }
    }
}

// ============== init 2: CG tensors (fp64 exact ref mirror) ==============
__device__ double cgval(int j1,int j2,int j3,int m1,int m2, const double* __restrict__ F, double pref0){
    int m3 = m1 + m2;
    if (abs(m3) > j3) return 0.0;
    double pref = pref0 * sqrt(F[j3+m3]*F[j3-m3]*F[j1-m1]*F[j1+m1]*F[j2-m2]*F[j2+m2]);
    int klo = max(0, max(j2-j3-m1, j1+m2-j3));
    int khi = min(j1+j2-j3, min(j1-m1, j2+m2));
    double s = 0.0;
    for (int k = klo; k <= khi; k++){
        double d = F[k]*F[j1+j2-j3-k]*F[j1-m1-k]*F[j2+m2-k]*F[j3-j2+m1+k]*F[j3-j1-m2+k];
        s += ((k & 1) ? -1.0 : 1.0) / d;
    }
    return pref * s;
}
__device__ __forceinline__ double w3j_entry(int j1,int j2,int j3,int mi,int ni,int ki,
                                            const double* __restrict__ F, double pref0, double inv2j3){
    int m1 = mi - j1, m2 = ni - j2, m3 = ki - j3;
    if (m1 + m2 + m3 != 0) return 0.0;
    double cg = cgval(j1, j2, j3, m1, m2, F, pref0);
    int e = j1 - j2 + m3;
    double sgn = (e & 1) ? -1.0 : 1.0;
    return sgn * cg * inv2j3;
}
__device__ __forceinline__ void qvalc(int l, int i, int j, double& re, double& im){
    re = 0.0; im = 0.0;
    const double s2 = 0.7071067811865476;
    int m = i - l;
    if (m == 0){ if (j == l) re = 1.0; return; }
    if (m > 0){
        if (j == l+m)      re = (m & 1) ? -s2 : s2;
        else if (j == l-m) re = s2;
    } else {
        int mm = -m;
        if (j == l-mm)      im = s2;
        else if (j == l+mm) im = (mm & 1) ? s2 : -s2;
    }
}
__device__ __forceinline__ int qcols(int l, int row, int* s){
    if (row == l){ s[0] = l; return 1; }
    s[0] = row; s[1] = 2*l - row; return 2;
}
__global__ void k_init_cg(){
    int tens = blockIdx.x;
    int lo = d_TLO[tens], li = d_TLI[tens], lf = d_TLF[tens];
    int da = 2*lo+1, db = 2*li+1, dc = 2*lf+1;
    int n = da*db*dc;
    __shared__ double sre[225], sim2[225];
    __shared__ double sF[12];
    __shared__ double s_pref0, s_inv2j3, s_nr, s_ni;
    if (threadIdx.x == 0){
        double f = 1.0;
        sF[0] = 1.0;
        for (int i = 1; i < 12; i++){ f *= (double)i; sF[i] = f; }
        s_pref0 = sqrt((double)(2*lf+1) * sF[lo+li-lf] * sF[lo-li+lf] * sF[-lo+li+lf] / sF[lo+li+lf+1]);
        s_inv2j3 = 1.0 / sqrt((double)(2*lf+1));
    }
    __syncthreads();
    const double* F = sF;
    for (int e = threadIdx.x; e < n; e += blockDim.x){
        int cc = e % dc; int ab = e / dc; int b = ab % db; int a = ab / db;
        int mset[2], nset[2], kset[2];
        int nm = qcols(lo, a, mset);
        int nn = qcols(li, b, nset);
        int nk = qcols(lf, cc, kset);
        double re = 0.0, imv = 0.0;
        for (int i1 = 0; i1 < nm; i1++){
            double q1r, q1i; qvalc(lo, a, mset[i1], q1r, q1i);
            for (int i2 = 0; i2 < nn; i2++){
                double q2r, q2i; qvalc(li, b, nset[i2], q2r, q2i);
                double q12r = q1r*q2r - q1i*q2i;
                double q12i = q1r*q2i + q1i*q2r;
                for (int i3 = 0; i3 < nk; i3++){
                    double q3r, q3i; qvalc(lf, cc, kset[i3], q3r, q3i);
                    double w = w3j_entry(lo, li, lf, mset[i1], nset[i2], kset[i3], F, s_pref0, s_inv2j3);
                    if (w != 0.0){
                        re  += (q12r*q3r - q12i*q3i) * w;
                        imv += (q12r*q3i + q12i*q3r) * w;
                    }
                }
            }
        }
        sre[e] = re; sim2[e] = imv;
    }
    __syncthreads();
    if (threadIdx.x == 0){
        double nr = 0.0, ni = 0.0;
        for (int e = 0; e < n; e++){ nr += sre[e]*sre[e]; ni += sim2[e]*sim2[e]; }
        s_nr = nr; s_ni = ni;
    }
    __syncthreads();
    bool use_re = (s_nr >= s_ni);
    double inv = 1.0 / sqrt(use_re ? s_nr : s_ni);
    int base = d_CGOFF[tens];
    for (int e = threadIdx.x; e < n; e += blockDim.x)
        g_CG[base + e] = (float)((use_re ? sre[e] : sim2[e]) * inv);
}

// ============== init 3: A/B tables, padded layout ==============
__global__ void k_init_ab(const float* __restrict__ W1, const float* __restrict__ b1,
                          const float* __restrict__ W2){
    int p  = blockIdx.x * 256 + threadIdx.x;
    int s0 = blockIdx.y * ABCHUNK;
    if (p >= NPATH) return;
    int pn = permute_pad(p);

    float A = 0.f, Bv = 0.f;
    for (int t = 0; t < HID; t++){
        float w = W1[t], bb = b1[t];
        int rk = g_rank[t];
        bool act = (w > 0.0f) ? (rk < s0) : ((w < 0.0f) ? (rk >= s0) : (bb > 0.0f));
        if (act){
            float w2 = W2[t*NPATH + p];
            A  = fmaf(w,  w2, A);
            Bv = fmaf(bb, w2, Bv);
        }
    }
    g_A[s0*NPAD + pn] = A;
    g_B[s0*NPAD + pn] = Bv;
    #pragma unroll
    for (int d = 1; d < ABCHUNK; d++){
        int s = s0 + d;
        if (s >= NSEG) break;
        int u  = g_sortIdx[s-1];
        float w = W1[u], bb = b1[u];
        float w2 = W2[u*NPATH + p];
        float sg = (w > 0.0f) ? 1.0f : ((w < 0.0f) ? -1.0f : 0.0f);
        A  = fmaf(sg*w,  w2, A);
        Bv = fmaf(sg*bb, w2, Bv);
        g_A[s*NPAD + pn] = A;
        g_B[s*NPAD + pn] = Bv;
    }
}

// ============== main: 288 threads, warp = 16 rows, 2 lanes/row ==============
// Per-warp PRIVATE stage: 16 rows x SPAD(65). No cross-warp coupling.
template<int NLF1, int NLF2>
__device__ __forceinline__ void point_rows(
    const float* __restrict__ sC, const float* __restrict__ sCY,
    float* __restrict__ wstg,          // this warp's private stage base
    float* __restrict__ out,           // out + z*20736
    int rl, int u, int i, int h, int l, int w,
    int PB0, int PB1, int PB2, int CY0, int CY1, int CY2)
{
    // ---- chunk A: li0 (db=1), stage cols 0..15 ----
    {
        float cy0 = sCY[CY0 + i];
        const float* cf = sC + PB0 + u;
        float* srow = wstg + rl*SPAD;
        #pragma unroll
        for (int vi = 0; vi < 8; vi++){
            int v = h*8 + vi;
            srow[v] = cy0 * cf[v*17];
        }
    }
    // ---- chunk A: li1 (db=3), stage cols 16..63 ----
    {
        float cy[NLF1*3];
        #pragma unroll
        for (int t = 0; t < NLF1*3; t++) cy[t] = sCY[CY1 + i*NLF1*3 + t];
        const float* cf = sC + PB1 + u;
        float* srow = wstg + rl*SPAD;
        #pragma unroll
        for (int vi = 0; vi < 8; vi++){
            int v = h*8 + vi;
            float cfk[NLF1];
            #pragma unroll
            for (int k = 0; k < NLF1; k++) cfk[k] = cf[(v*NLF1+k)*17];
            #pragma unroll
            for (int j = 0; j < 3; j++){
                float acc = 0.f;
                #pragma unroll
                for (int k = 0; k < NLF1; k++) acc = fmaf(cy[k*3+j], cfk[k], acc);
                srow[16 + v*3 + j] = acc;
            }
        }
    }
    __syncwarp();
    // ---- flush A: this warp's 16 rows, out cols 0..63 ----
    #pragma unroll 4
    for (int it = 0; it < 32; it++){
        int t = it*32 + l;
        int rl2 = t >> 6, c = t & 63;
        float val = wstg[rl2*SPAD + c];
        __stcs(out + (w*16 + rl2)*144 + c, val);
    }
    __syncwarp();
    // ---- chunk B: li2 (db=5), out cols 64..143, two 40-col subchunks ----
    float cy[NLF2*5];
    #pragma unroll
    for (int t = 0; t < NLF2*5; t++) cy[t] = sCY[CY2 + i*NLF2*5 + t];
    const float* cf = sC + PB2 + u;
    #pragma unroll
    for (int s = 0; s < 2; s++){
        float* srow = wstg + rl*SPAD;
        #pragma unroll
        for (int vi = 0; vi < 4; vi++){
            int v  = s*8 + h*4 + vi;
            int cb = (h*4 + vi)*5;
            float cfk[NLF2];
            #pragma unroll
            for (int k = 0; k < NLF2; k++) cfk[k] = cf[(v*NLF2+k)*17];
            #pragma unroll
            for (int j = 0; j < 5; j++){
                float acc = 0.f;
                #pragma unroll
                for (int k = 0; k < NLF2; k++) acc = fmaf(cy[k*5+j], cfk[k], acc);
                srow[cb + j] = acc;
            }
        }
        __syncwarp();
        #pragma unroll 4
        for (int it = 0; it < 20; it++){
            int t = it*32 + l;
            int rl2 = t / 40, cl2 = t - rl2*40;
            float val = wstg[rl2*SPAD + cl2];
            __stcs(out + (w*16 + rl2)*144 + 64 + s*40 + cl2, val);
        }
        __syncwarp();
    }
}

extern __shared__ float smem[];

__global__ __launch_bounds__(288, 3)
void k_main(const float* __restrict__ r, float* __restrict__ out){
    float* sStage = smem;                    // 9 warps * 16*SPAD = 9360 floats
    float* sC     = smem + 9*16*SPAD;        // NPAD (byte offset 37440, 16B aligned)
    float* sY     = sC + NPAD;               // 32
    float* sCY    = sY + 32;                 // 260

    int z   = blockIdx.x;
    int tid = threadIdx.x;
    int w   = tid >> 5, l = tid & 31;
    int rl  = l >> 1, h = l & 1;
    int row = w*16 + rl;

    float x = r[3*z+0], y = r[3*z+1], zz = r[3*z+2];
    float rad = sqrtf(x*x + y*y + zz*zz);
    bool  iszero = (rad == 0.0f);
    float inv = 1.0f / fmaxf(rad, 1e-12f);
    float ux = x*inv, uy = y*inv, uz = zz*inv;

    if (tid == 0){
        float X = ux, Y = uy, Z = uz;
        float X2 = X*X, Y2 = Y*Y, Z2 = Z*Z;
        sY[0]  = 0.28209479177387814f;
        sY[1]  = 0.4886025119029199f * Y;
        sY[2]  = 0.4886025119029199f * Z;
        sY[3]  = 0.4886025119029199f * X;
        sY[4]  = 1.0925484305920792f * X*Y;
        sY[5]  = 1.0925484305920792f * Y*Z;
        sY[6]  = 0.31539156525252005f * (3.f*Z2 - 1.f);
        sY[7]  = 1.0925484305920792f * X*Z;
        sY[8]  = 0.5462742152960396f * (X2 - Y2);
        sY[9]  = 0.5900435899266435f * Y*(3.f*X2 - Y2);
        sY[10] = 2.890611442640554f  * X*Y*Z;
        sY[11] = 0.4570457994644658f * Y*(5.f*Z2 - 1.f);
        sY[12] = 0.3731763325901154f * Z*(5.f*Z2 - 3.f);
        sY[13] = 0.4570457994644658f * X*(5.f*Z2 - 1.f);
        sY[14] = 1.445305721320277f  * (X2 - Y2)*Z;
        sY[15] = 0.5900435899266435f * X*(X2 - 3.f*Y2);
        sY[16] = 2.5033429417967046f * X*Y*(X2 - Y2);
        sY[17] = 1.7701307697799304f * Y*(3.f*X2 - Y2)*Z;
        sY[18] = 0.9461746957575601f * X*Y*(7.f*Z2 - 1.f);
        sY[19] = 0.6690465435572892f * Y*Z*(7.f*Z2 - 3.f);
        sY[20] = 0.10578554691520431f * (35.f*Z2*Z2 - 30.f*Z2 + 3.f);
        sY[21] = 0.6690465435572892f * X*Z*(7.f*Z2 - 3.f);
        sY[22] = 0.47308734787878004f * (X2 - Y2)*(7.f*Z2 - 1.f);
        sY[23] = 1.7701307697799304f * X*(X2 - 3.f*Y2)*Z;
        sY[24] = 0.6258357354491761f * (X2*X2 - 6.f*X2*Y2 + Y2*Y2);
    }

    bool pred = (tid < HID) && (g_T[tid] < rad);
    int seg = __syncthreads_count(pred);     // barrier: sY visible

    // coeff fill (padded layout), float4
    {
        const float4* A4 = (const float4*)(g_A + (size_t)seg * NPAD);
        const float4* B4 = (const float4*)(g_B + (size_t)seg * NPAD);
        float4* sC4 = (float4*)sC;
        #pragma unroll
        for (int it = 0; it < 5; it++){
            int idx = it*288 + tid;
            if (idx < NPAD/4){
                float4 a = __ldg(&A4[idx]);
                float4 b = __ldg(&B4[idx]);
                sC4[idx] = make_float4(fmaf(rad,a.x,b.x), fmaf(rad,a.y,b.y),
                                       fmaf(rad,a.z,b.z), fmaf(rad,a.w,b.w));
            }
        }
    }

    // CY = norm * (C . Y)
    if (tid < 259){
        int desc = g_slotdesc[tid];
        int cgbase = desc & 0xFFF;
        int yoff   = (desc >> 12) & 0x1F;
        int dc     = (desc >> 17) & 0x1F;
        int pair   = desc >> 22;
        int lo = pair / 3, li = pair - lo*3;
        float v = 0.f;
        for (int m = 0; m < dc; m++)
            v = fmaf(g_CG[cgbase + m], sY[yoff + m], v);
        float lm = sqrtf((float)(2*li+1) * 12.566370614359172f);
        float num = (lo == 0) ? 48.f : ((lo == 1) ? 112.f : 144.f);
        float nrm = iszero ? (lm * 0.25f) : (lm * rsqrtf(num));
        sCY[tid] = v * nrm;
    }
    __syncthreads();

    float* outz = out + (size_t)z * 20736;
    float* wstg = sStage + w * (16*SPAD);
    if (w == 0){
        point_rows<1,1>(sC, sCY, wstg, outz, rl, row, 0, h, l, w,
                        0, 272, 544, 0, 1, 4);
    } else if (w < 4){
        int t = row - 16; int u = t/3, i = t - u*3;
        point_rows<3,3>(sC, sCY, wstg, outz, rl, u, i, h, l, w,
                        816, 1088, 1904, 9, 12, 39);
    } else {
        int t = row - 64; int u = t/5, i = t - u*5;
        point_rows<3,5>(sC, sCY, wstg, outz, rl, u, i, h, l, w,
                        2720, 2992, 3808, 84, 89, 134);
    }
}

extern "C" void kernel_launch(void* const* d_in, const int* in_sizes, int n_in,
                              void* d_out, int out_size){
    const float* r  = (const float*)d_in[0];
    const float* W1 = (const float*)d_in[1];
    const float* b1 = (const float*)d_in[2];
    const float* W2 = (const float*)d_in[3];
    float* out = (float*)d_out;

    static bool attr_set = false;
    int smem_bytes = (9*16*SPAD + NPAD + 32 + 260) * 4;
    if (!attr_set){
        cudaFuncSetAttribute(k_main, cudaFuncAttributeMaxDynamicSharedMemorySize, smem_bytes);
        attr_set = true;
    }

    k_init_sort<<<1, 128>>>(W1, b1);
    k_init_cg<<<19, 128>>>();
    dim3 abgrid((NPATH + 255)/256, (NSEG + ABCHUNK - 1)/ABCHUNK);
    k_init_ab<<<abgrid, 256>>>(W1, b1, W2);
    k_main<<<8192, 288, smem_bytes>>>(r, out);
}

// round 9
// speedup vs baseline: 2.1141x; 1.3307x over previous
#include <cuda_runtime.h>
#include <math.h>
#include <stdint.h>

#define HID     100
#define NPATH   4864
#define NPAD    5168          // padded coeff table (stride 17 per u-group)
#define NSEG    101
#define ABCHUNK 8

// ---------------- static device scratch ----------------
__device__ float g_T[HID];
__device__ int   g_sortIdx[HID];
__device__ int   g_rank[HID];
__device__ float g_CG[1225];
__device__ int   g_slotdesc[259];
__device__ __align__(16) float g_A[NSEG*NPAD];
__device__ __align__(16) float g_B[NSEG*NPAD];

__constant__ int d_NLF[9]   = {1,1,1, 1,3,3, 1,3,5};
__constant__ int d_TBASE[9] = {0,1,2, 3,4,7, 10,11,14};
__constant__ int d_CGOFF[19]= {0,1,10,35,44,53,80,125,170,245,350,375,420,495,600,625,700,825,1000};
__constant__ int d_TLO[19]  = {0,0,0,1,1,1,1,1,1,1,2,2,2,2,2,2,2,2,2};
__constant__ int d_TLI[19]  = {0,1,2,0,1,1,1,2,2,2,0,1,1,1,2,2,2,2,2};
__constant__ int d_TLF[19]  = {0,1,2,1,0,1,2,1,2,3,2,1,2,3,0,1,2,3,4};

// original path index -> padded-permuted index: (v*nlf+k)*17 + u
__device__ __forceinline__ int permute_pad(int p){
    int base, nlf, pb17;
    if      (p < 256)  { base = 0;    nlf = 1; pb17 = 0;    }
    else if (p < 512)  { base = 256;  nlf = 1; pb17 = 272;  }
    else if (p < 768)  { base = 512;  nlf = 1; pb17 = 544;  }
    else if (p < 1024) { base = 768;  nlf = 1; pb17 = 816;  }
    else if (p < 1792) { base = 1024; nlf = 3; pb17 = 1088; }
    else if (p < 2560) { base = 1792; nlf = 3; pb17 = 1904; }
    else if (p < 2816) { base = 2560; nlf = 1; pb17 = 2720; }
    else if (p < 3584) { base = 2816; nlf = 3; pb17 = 2992; }
    else               { base = 3584; nlf = 5; pb17 = 3808; }
    int local = p - base;
    int u   = local / (16*nlf);
    int rem = local - u*16*nlf;
    return pb17 + rem*17 + u;
}

// ============== init 1 ==============
__global__ void k_init_sort(const float* __restrict__ W1, const float* __restrict__ b1){
    int t = threadIdx.x;
    __shared__ float th[HID];
    if (t < HID){
        float w = W1[t];
        th[t] = (w != 0.0f) ? (-b1[t] / w) : -1e30f;
    }
    __syncthreads();
    if (t < HID){
        float mine = th[t];
        int rank = 0;
        for (int i = 0; i < HID; i++){
            float o = th[i];
            rank += (o < mine) || (o == mine && i < t);
        }
        g_T[rank] = mine;
        g_sortIdx[rank] = t;
        g_rank[t] = rank;
    }
    if (t == 0){
        int s = 0;
        for (int pair = 0; pair < 9; pair++){
            int lo = pair / 3, li = pair % 3;
            int da = 2*lo+1, db = 2*li+1;
            int nlf = d_NLF[pair];
            int lfmin = (lo > li) ? lo - li : li - lo;
            for (int a = 0; a < da; a++)
                for (int k = 0; k < nlf; k++)
                    for (int b = 0; b < db; b++){
                        int lf = lfmin + k;
                        int cgbase = d_CGOFF[d_TBASE[pair]+k] + (a*db + b)*(2*lf+1);
                        g_slotdesc[s++] = cgbase | ((lf*lf) << 12) | ((2*lf+1) << 17) | (pair << 22);
                    }
        }
    }
}

// ============== init 2: CG tensors (fp32, reciprocal factorial table) ==============
__device__ float cgvalf(int j1,int j2,int j3,int m1,int m2,
                        const float* __restrict__ F, const float* __restrict__ Fi,
                        float pref0){
    int m3 = m1 + m2;
    if (abs(m3) > j3) return 0.f;
    float pref = pref0 * sqrtf(F[j3+m3]*F[j3-m3]*F[j1-m1]*F[j1+m1]*F[j2-m2]*F[j2+m2]);
    int klo = max(0, max(j2-j3-m1, j1+m2-j3));
    int khi = min(j1+j2-j3, min(j1-m1, j2+m2));
    float s = 0.f;
    for (int k = klo; k <= khi; k++){
        float d = Fi[k]*Fi[j1+j2-j3-k]*Fi[j1-m1-k]*Fi[j2+m2-k]*Fi[j3-j2+m1+k]*Fi[j3-j1-m2+k];
        s += (k & 1) ? -d : d;
    }
    return pref * s;
}
__device__ __forceinline__ float w3j_entryf(int j1,int j2,int j3,int mi,int ni,int ki,
                                            const float* __restrict__ F, const float* __restrict__ Fi,
                                            float pref0, float inv2j3){
    int m1 = mi - j1, m2 = ni - j2, m3 = ki - j3;
    if (m1 + m2 + m3 != 0) return 0.f;
    float cg = cgvalf(j1, j2, j3, m1, m2, F, Fi, pref0);
    float sgn = ((j1 - j2 + m3) & 1) ? -1.f : 1.f;
    return sgn * cg * inv2j3;
}
__device__ __forceinline__ void qvalcf(int l, int i, int j, float& re, float& im){
    re = 0.f; im = 0.f;
    const float s2 = 0.70710678118654752f;
    int m = i - l;
    if (m == 0){ if (j == l) re = 1.f; return; }
    if (m > 0){
        if (j == l+m)      re = (m & 1) ? -s2 : s2;
        else if (j == l-m) re = s2;
    } else {
        int mm = -m;
        if (j == l-mm)      im = s2;
        else if (j == l+mm) im = (mm & 1) ? s2 : -s2;
    }
}
__device__ __forceinline__ int qcols(int l, int row, int* s){
    if (row == l){ s[0] = l; return 1; }
    s[0] = row; s[1] = 2*l - row; return 2;
}
__global__ void k_init_cg(){
    int tens = blockIdx.x;
    int lo = d_TLO[tens], li = d_TLI[tens], lf = d_TLF[tens];
    int da = 2*lo+1, db = 2*li+1, dc = 2*lf+1;
    int n = da*db*dc;
    __shared__ float sre[225], sim2[225];
    __shared__ float sF[12], sFi[12];
    __shared__ float s_pref0, s_inv2j3, s_nr, s_ni;
    if (threadIdx.x == 0){
        float f = 1.f;
        sF[0] = 1.f; sFi[0] = 1.f;
        for (int i = 1; i < 12; i++){ f *= (float)i; sF[i] = f; sFi[i] = 1.f/f; }
        s_pref0 = sqrtf((float)(2*lf+1) * sF[lo+li-lf] * sF[lo-li+lf] * sF[-lo+li+lf] * sFi[lo+li+lf+1]);
        s_inv2j3 = rsqrtf((float)(2*lf+1));
    }
    __syncthreads();
    const float* F = sF; const float* Fi = sFi;
    for (int e = threadIdx.x; e < n; e += blockDim.x){
        int cc = e % dc; int ab = e / dc; int b = ab % db; int a = ab / db;
        int mset[2], nset[2], kset[2];
        int nm = qcols(lo, a, mset);
        int nn = qcols(li, b, nset);
        int nk = qcols(lf, cc, kset);
        float re = 0.f, imv = 0.f;
        for (int i1 = 0; i1 < nm; i1++){
            float q1r, q1i; qvalcf(lo, a, mset[i1], q1r, q1i);
            for (int i2 = 0; i2 < nn; i2++){
                float q2r, q2i; qvalcf(li, b, nset[i2], q2r, q2i);
                float q12r = q1r*q2r - q1i*q2i;
                float q12i = q1r*q2i + q1i*q2r;
                for (int i3 = 0; i3 < nk; i3++){
                    float q3r, q3i; qvalcf(lf, cc, kset[i3], q3r, q3i);
                    float w = w3j_entryf(lo, li, lf, mset[i1], nset[i2], kset[i3], F, Fi, s_pref0, s_inv2j3);
                    if (w != 0.f){
                        re  += (q12r*q3r - q12i*q3i) * w;
                        imv += (q12r*q3i + q12i*q3r) * w;
                    }
                }
            }
        }
        sre[e] = re; sim2[e] = imv;
    }
    __syncthreads();
    if (threadIdx.x == 0){
        float nr = 0.f, ni = 0.f;
        for (int e = 0; e < n; e++){ nr += sre[e]*sre[e]; ni += sim2[e]*sim2[e]; }
        s_nr = nr; s_ni = ni;
    }
    __syncthreads();
    bool use_re = (s_nr >= s_ni);
    float inv = rsqrtf(use_re ? s_nr : s_ni);
    int base = d_CGOFF[tens];
    for (int e = threadIdx.x; e < n; e += blockDim.x)
        g_CG[base + e] = (use_re ? sre[e] : sim2[e]) * inv;
}

// ============== init 3: A/B tables, padded layout ==============
__global__ void k_init_ab(const float* __restrict__ W1, const float* __restrict__ b1,
                          const float* __restrict__ W2){
    int p  = blockIdx.x * 256 + threadIdx.x;
    int s0 = blockIdx.y * ABCHUNK;
    if (p >= NPATH) return;
    int pn = permute_pad(p);

    float A = 0.f, Bv = 0.f;
    for (int t = 0; t < HID; t++){
        float w = W1[t], bb = b1[t];
        int rk = g_rank[t];
        bool act = (w > 0.0f) ? (rk < s0) : ((w < 0.0f) ? (rk >= s0) : (bb > 0.0f));
        if (act){
            float w2 = W2[t*NPATH + p];
            A  = fmaf(w,  w2, A);
            Bv = fmaf(bb, w2, Bv);
        }
    }
    g_A[s0*NPAD + pn] = A;
    g_B[s0*NPAD + pn] = Bv;
    #pragma unroll
    for (int d = 1; d < ABCHUNK; d++){
        int s = s0 + d;
        if (s >= NSEG) break;
        int u  = g_sortIdx[s-1];
        float w = W1[u], bb = b1[u];
        float w2 = W2[u*NPATH + p];
        float sg = (w > 0.0f) ? 1.0f : ((w < 0.0f) ? -1.0f : 0.0f);
        A  = fmaf(sg*w,  w2, A);
        Bv = fmaf(sg*bb, w2, Bv);
        g_A[s*NPAD + pn] = A;
        g_B[s*NPAD + pn] = Bv;
    }
}

// ============== main: lane-owns-column, direct coalesced STG ==============
// out[(lo,u,i),(li,v,j)] = sum_k CY[(i*nlf+k)*db+j] * coeff[(v*nlf+k)*17+u]
// cy loaded ROTATED by i0 so the row loop indexes cy[(rr % NI)] (compile-time).
// cf (nlf values) reloaded only when u advances (warp-uniform predicate).
template<int NI, int NLF, int DB, int NROWS>
__device__ __forceinline__ void pass(const float* __restrict__ cyb,   // sCY + CYb + j
                                     const float* __restrict__ cfb,   // sC + PB + v*NLF*17 + u0
                                     float* __restrict__ outp,        // out + row0*144 + c
                                     int i0){
    float cy[NI*NLF];
    #pragma unroll
    for (int m = 0; m < NI; m++){
        int irot = i0 + m; if (irot >= NI) irot -= NI;
        #pragma unroll
        for (int k = 0; k < NLF; k++)
            cy[m*NLF + k] = cyb[(irot*NLF + k)*DB];
    }
    float cf[NLF];
    #pragma unroll
    for (int k = 0; k < NLF; k++) cf[k] = cfb[k*17];
    int icur = i0, uoff = 0;
    #pragma unroll
    for (int rr = 0; rr < NROWS; rr++){
        float val = 0.f;
        #pragma unroll
        for (int k = 0; k < NLF; k++) val = fmaf(cy[(rr % NI)*NLF + k], cf[k], val);
        __stcs(outp + rr*144, val);
        if (rr != NROWS-1){
            if (++icur == NI){
                icur = 0; uoff++;
                #pragma unroll
                for (int k = 0; k < NLF; k++) cf[k] = cfb[k*17 + uoff];
            }
        }
    }
}

template<int NI, int NLF1, int NLF2>
__device__ __forceinline__ void warp_work(const float* __restrict__ sC,
                                          const float* __restrict__ sCY,
                                          float* __restrict__ outz,
                                          int w, int l, int u0, int i0,
                                          int PB0, int PB1, int PB2,
                                          int CY0, int CY1, int CY2){
    float* outw = outz + w*16*144;
    int c16  = l & 15, half = l >> 4;
    int iadj = i0 + 8*half;
    int u0h  = u0 + iadj / NI;
    int i0h  = iadj - (iadj / NI) * NI;
    float* outh = outw + half*8*144;

    // li0 split pass (cols 0..15), 8 rows per lane
    pass<NI,1,1,8>(sCY + CY0, sC + PB0 + c16*17 + u0h, outh + c16, i0h);
    // li1 full pass (cols 16..47)
    { int cc = l; int v = cc/3, j = cc - 3*v;
      pass<NI,NLF1,3,16>(sCY + CY1 + j, sC + PB1 + (v*NLF1)*17 + u0, outw + 16 + cc, i0); }
    // li1 split pass (cols 48..63)
    { int cc = 32 + c16; int v = cc/3, j = cc - 3*v;
      pass<NI,NLF1,3,8>(sCY + CY1 + j, sC + PB1 + (v*NLF1)*17 + u0h, outh + 16 + cc, i0h); }
    // li2 full passes (cols 64..95, 96..127)
    { int cc = l; int v = cc/5, j = cc - 5*v;
      pass<NI,NLF2,5,16>(sCY + CY2 + j, sC + PB2 + (v*NLF2)*17 + u0, outw + 64 + cc, i0); }
    { int cc = 32 + l; int v = cc/5, j = cc - 5*v;
      pass<NI,NLF2,5,16>(sCY + CY2 + j, sC + PB2 + (v*NLF2)*17 + u0, outw + 64 + cc, i0); }
    // li2 split pass (cols 128..143)
    { int cc = 64 + c16; int v = cc/5, j = cc - 5*v;
      pass<NI,NLF2,5,8>(sCY + CY2 + j, sC + PB2 + (v*NLF2)*17 + u0h, outh + 64 + cc, i0h); }
}

extern __shared__ float smem[];

__global__ __launch_bounds__(288, 4)
void k_main(const float* __restrict__ r, float* __restrict__ out){
    float* sC  = smem;            // NPAD floats
    float* sY  = sC + NPAD;       // 32
    float* sCY = sY + 32;         // 260

    int z   = blockIdx.x;
    int tid = threadIdx.x;
    int w   = tid >> 5, l = tid & 31;

    float x = r[3*z+0], y = r[3*z+1], zz = r[3*z+2];
    float rad = sqrtf(x*x + y*y + zz*zz);
    bool  iszero = (rad == 0.0f);
    float inv = 1.0f / fmaxf(rad, 1e-12f);
    float ux = x*inv, uy = y*inv, uz = zz*inv;

    if (tid == 0){
        float X = ux, Y = uy, Z = uz;
        float X2 = X*X, Y2 = Y*Y, Z2 = Z*Z;
        sY[0]  = 0.28209479177387814f;
        sY[1]  = 0.4886025119029199f * Y;
        sY[2]  = 0.4886025119029199f * Z;
        sY[3]  = 0.4886025119029199f * X;
        sY[4]  = 1.0925484305920792f * X*Y;
        sY[5]  = 1.0925484305920792f * Y*Z;
        sY[6]  = 0.31539156525252005f * (3.f*Z2 - 1.f);
        sY[7]  = 1.0925484305920792f * X*Z;
        sY[8]  = 0.5462742152960396f * (X2 - Y2);
        sY[9]  = 0.5900435899266435f * Y*(3.f*X2 - Y2);
        sY[10] = 2.890611442640554f  * X*Y*Z;
        sY[11] = 0.4570457994644658f * Y*(5.f*Z2 - 1.f);
        sY[12] = 0.3731763325901154f * Z*(5.f*Z2 - 3.f);
        sY[13] = 0.4570457994644658f * X*(5.f*Z2 - 1.f);
        sY[14] = 1.445305721320277f  * (X2 - Y2)*Z;
        sY[15] = 0.5900435899266435f * X*(X2 - 3.f*Y2);
        sY[16] = 2.5033429417967046f * X*Y*(X2 - Y2);
        sY[17] = 1.7701307697799304f * Y*(3.f*X2 - Y2)*Z;
        sY[18] = 0.9461746957575601f * X*Y*(7.f*Z2 - 1.f);
        sY[19] = 0.6690465435572892f * Y*Z*(7.f*Z2 - 3.f);
        sY[20] = 0.10578554691520431f * (35.f*Z2*Z2 - 30.f*Z2 + 3.f);
        sY[21] = 0.6690465435572892f * X*Z*(7.f*Z2 - 3.f);
        sY[22] = 0.47308734787878004f * (X2 - Y2)*(7.f*Z2 - 1.f);
        sY[23] = 1.7701307697799304f * X*(X2 - 3.f*Y2)*Z;
        sY[24] = 0.6258357354491761f * (X2*X2 - 6.f*X2*Y2 + Y2*Y2);
    }

    bool pred = (tid < HID) && (g_T[tid] < rad);
    int seg = __syncthreads_count(pred);     // barrier: sY visible

    // coeff fill (padded-permuted layout), float4
    {
        const float4* A4 = (const float4*)(g_A + (size_t)seg * NPAD);
        const float4* B4 = (const float4*)(g_B + (size_t)seg * NPAD);
        float4* sC4 = (float4*)sC;
        #pragma unroll
        for (int it = 0; it < 5; it++){
            int idx = it*288 + tid;
            if (idx < NPAD/4){
                float4 a = __ldg(&A4[idx]);
                float4 b = __ldg(&B4[idx]);
                sC4[idx] = make_float4(fmaf(rad,a.x,b.x), fmaf(rad,a.y,b.y),
                                       fmaf(rad,a.z,b.z), fmaf(rad,a.w,b.w));
            }
        }
    }

    // CY = norm * (C . Y)
    if (tid < 259){
        int desc = g_slotdesc[tid];
        int cgbase = desc & 0xFFF;
        int yoff   = (desc >> 12) & 0x1F;
        int dc     = (desc >> 17) & 0x1F;
        int pair   = desc >> 22;
        int lo = pair / 3, li = pair - lo*3;
        float v = 0.f;
        for (int m = 0; m < dc; m++)
            v = fmaf(g_CG[cgbase + m], sY[yoff + m], v);
        float lm = sqrtf((float)(2*li+1) * 12.566370614359172f);
        float num = (lo == 0) ? 48.f : ((lo == 1) ? 112.f : 144.f);
        float nrm = iszero ? (lm * 0.25f) : (lm * rsqrtf(num));
        sCY[tid] = v * nrm;
    }
    __syncthreads();

    float* outz = out + (size_t)z * 20736;
    if (w == 0){
        warp_work<1,1,1>(sC, sCY, outz, w, l, 0, 0,
                         0, 272, 544, 0, 1, 4);
    } else if (w < 4){
        int rel = (w-1)*16;
        warp_work<3,3,3>(sC, sCY, outz, w, l, rel/3, rel - (rel/3)*3,
                         816, 1088, 1904, 9, 12, 39);
    } else {
        int rel = (w-4)*16;
        warp_work<5,3,5>(sC, sCY, outz, w, l, rel/5, rel - (rel/5)*5,
                         2720, 2992, 3808, 84, 89, 134);
    }
}

extern "C" void kernel_launch(void* const* d_in, const int* in_sizes, int n_in,
                              void* d_out, int out_size){
    const float* r  = (const float*)d_in[0];
    const float* W1 = (const float*)d_in[1];
    const float* b1 = (const float*)d_in[2];
    const float* W2 = (const float*)d_in[3];
    float* out = (float*)d_out;

    static bool attr_set = false;
    int smem_bytes = (NPAD + 32 + 260) * 4;
    if (!attr_set){
        cudaFuncSetAttribute(k_main, cudaFuncAttributeMaxDynamicSharedMemorySize, smem_bytes);
        attr_set = true;
    }

    k_init_sort<<<1, 128>>>(W1, b1);
    k_init_cg<<<19, 128>>>();
    dim3 abgrid((NPATH + 255)/256, (NSEG + ABCHUNK - 1)/ABCHUNK);
    k_init_ab<<<abgrid, 256>>>(W1, b1, W2);
    k_main<<<8192, 288, smem_bytes>>>(r, out);
}

// round 10
// speedup vs baseline: 2.5656x; 1.2136x over previous
#include <cuda_runtime.h>
#include <math.h>
#include <stdint.h>

#define HID     100
#define NPATH   4864
#define NPAD    6800          // k-padded coeff table: per pair (v*17+u)*KP+k
#define NSEG    101
#define NCYT    376           // k-padded CY table
#define ABCHUNK 8

// ---------------- static device scratch (zero-initialized -> pads stay 0) ----------------
__device__ float g_T[HID];
__device__ int   g_sortIdx[HID];
__device__ int   g_rank[HID];
__device__ float g_CG[1225];
__device__ int   g_slotdesc[259];
__device__ __align__(16) float g_A[NSEG*NPAD];
__device__ __align__(16) float g_B[NSEG*NPAD];

__constant__ int d_NLF[9]   = {1,1,1, 1,3,3, 1,3,5};
__constant__ int d_KP[9]    = {1,1,1, 1,4,4, 1,4,8};
__constant__ int d_TBASE[9] = {0,1,2, 3,4,7, 10,11,14};
__constant__ int d_CYTB[9]  = {0,1,4, 9,12,48, 108,116,176};
__constant__ int d_CGOFF[19]= {0,1,10,35,44,53,80,125,170,245,350,375,420,495,600,625,700,825,1000};
__constant__ int d_TLO[19]  = {0,0,0,1,1,1,1,1,1,1,2,2,2,2,2,2,2,2,2};
__constant__ int d_TLI[19]  = {0,1,2,0,1,1,1,2,2,2,0,1,1,1,2,2,2,2,2};
__constant__ int d_TLF[19]  = {0,1,2,1,0,1,2,1,2,3,2,1,2,3,0,1,2,3,4};

// original path index -> padded layout index
__device__ __forceinline__ int permute_pad(int p){
    int base, nlf, kp, pbn;
    if      (p < 256)  { base=0;    nlf=1; kp=1; pbn=0;    }
    else if (p < 512)  { base=256;  nlf=1; kp=1; pbn=272;  }
    else if (p < 768)  { base=512;  nlf=1; kp=1; pbn=544;  }
    else if (p < 1024) { base=768;  nlf=1; kp=1; pbn=816;  }
    else if (p < 1792) { base=1024; nlf=3; kp=4; pbn=1088; }
    else if (p < 2560) { base=1792; nlf=3; kp=4; pbn=2176; }
    else if (p < 2816) { base=2560; nlf=1; kp=1; pbn=3264; }
    else if (p < 3584) { base=2816; nlf=3; kp=4; pbn=3536; }
    else               { base=3584; nlf=5; kp=8; pbn=4624; }
    int local = p - base;
    int u   = local / (16*nlf);
    int rem = local - u*16*nlf;
    int v = rem / nlf, k = rem - v*nlf;
    return pbn + (v*17 + u)*kp + k;
}

// ============== init: CG tensors (blocks 0-18) + sort/desc (block 19) ==============
__device__ float cgvalf(int j1,int j2,int j3,int m1,int m2,
                        const float* __restrict__ F, const float* __restrict__ Fi,
                        float pref0){
    int m3 = m1 + m2;
    if (abs(m3) > j3) return 0.f;
    float pref = pref0 * sqrtf(F[j3+m3]*F[j3-m3]*F[j1-m1]*F[j1+m1]*F[j2-m2]*F[j2+m2]);
    int klo = max(0, max(j2-j3-m1, j1+m2-j3));
    int khi = min(j1+j2-j3, min(j1-m1, j2+m2));
    float s = 0.f;
    for (int k = klo; k <= khi; k++){
        float d = Fi[k]*Fi[j1+j2-j3-k]*Fi[j1-m1-k]*Fi[j2+m2-k]*Fi[j3-j2+m1+k]*Fi[j3-j1-m2+k];
        s += (k & 1) ? -d : d;
    }
    return pref * s;
}
__device__ __forceinline__ float w3j_entryf(int j1,int j2,int j3,int mi,int ni,int ki,
                                            const float* __restrict__ F, const float* __restrict__ Fi,
                                            float pref0, float inv2j3){
    int m1 = mi - j1, m2 = ni - j2, m3 = ki - j3;
    if (m1 + m2 + m3 != 0) return 0.f;
    float cg = cgvalf(j1, j2, j3, m1, m2, F, Fi, pref0);
    float sgn = ((j1 - j2 + m3) & 1) ? -1.f : 1.f;
    return sgn * cg * inv2j3;
}
__device__ __forceinline__ void qvalcf(int l, int i, int j, float& re, float& im){
    re = 0.f; im = 0.f;
    const float s2 = 0.70710678118654752f;
    int m = i - l;
    if (m == 0){ if (j == l) re = 1.f; return; }
    if (m > 0){
        if (j == l+m)      re = (m & 1) ? -s2 : s2;
        else if (j == l-m) re = s2;
    } else {
        int mm = -m;
        if (j == l-mm)      im = s2;
        else if (j == l+mm) im = (mm & 1) ? s2 : -s2;
    }
}
__device__ __forceinline__ int qcols(int l, int row, int* s){
    if (row == l){ s[0] = l; return 1; }
    s[0] = row; s[1] = 2*l - row; return 2;
}
__global__ void k_init_cgsort(const float* __restrict__ W1, const float* __restrict__ b1){
    if (blockIdx.x == 19){
        int t = threadIdx.x;
        __shared__ float th[HID];
        if (t < HID){
            float w = W1[t];
            th[t] = (w != 0.0f) ? (-b1[t] / w) : -1e30f;
        }
        __syncthreads();
        if (t < HID){
            float mine = th[t];
            int rank = 0;
            for (int i = 0; i < HID; i++){
                float o = th[i];
                rank += (o < mine) || (o == mine && i < t);
            }
            g_T[rank] = mine;
            g_sortIdx[rank] = t;
            g_rank[t] = rank;
        }
        if (t == 0){
            int s = 0;
            for (int pair = 0; pair < 9; pair++){
                int lo = pair/3, li = pair%3;
                int da = 2*lo+1, db = 2*li+1;
                int nlf = d_NLF[pair], kp = d_KP[pair];
                int lfmin = (lo > li) ? lo - li : li - lo;
                for (int a = 0; a < da; a++)
                    for (int k = 0; k < nlf; k++)
                        for (int b = 0; b < db; b++){
                            int lf = lfmin + k;
                            int cgbase = d_CGOFF[d_TBASE[pair]+k] + (a*db + b)*(2*lf+1);
                            int tgt = d_CYTB[pair] + (b*da + a)*kp + k;
                            g_slotdesc[s++] = cgbase | (lf<<11) | (lo<<14) | (li<<16) | (tgt<<18);
                        }
            }
        }
        return;
    }
    int tens = blockIdx.x;
    int lo = d_TLO[tens], li = d_TLI[tens], lf = d_TLF[tens];
    int da = 2*lo+1, db = 2*li+1, dc = 2*lf+1;
    int n = da*db*dc;
    __shared__ float sre[225], sim2[225];
    __shared__ float sF[12], sFi[12];
    __shared__ float s_pref0, s_inv2j3, s_nr, s_ni;
    if (threadIdx.x == 0){
        float f = 1.f;
        sF[0] = 1.f; sFi[0] = 1.f;
        for (int i = 1; i < 12; i++){ f *= (float)i; sF[i] = f; sFi[i] = 1.f/f; }
        s_pref0 = sqrtf((float)(2*lf+1) * sF[lo+li-lf] * sF[lo-li+lf] * sF[-lo+li+lf] * sFi[lo+li+lf+1]);
        s_inv2j3 = rsqrtf((float)(2*lf+1));
    }
    __syncthreads();
    const float* F = sF; const float* Fi = sFi;
    for (int e = threadIdx.x; e < n; e += blockDim.x){
        int cc = e % dc; int ab = e / dc; int b = ab % db; int a = ab / db;
        int mset[2], nset[2], kset[2];
        int nm = qcols(lo, a, mset);
        int nn = qcols(li, b, nset);
        int nk = qcols(lf, cc, kset);
        float re = 0.f, imv = 0.f;
        for (int i1 = 0; i1 < nm; i1++){
            float q1r, q1i; qvalcf(lo, a, mset[i1], q1r, q1i);
            for (int i2 = 0; i2 < nn; i2++){
                float q2r, q2i; qvalcf(li, b, nset[i2], q2r, q2i);
                float q12r = q1r*q2r - q1i*q2i;
                float q12i = q1r*q2i + q1i*q2r;
                for (int i3 = 0; i3 < nk; i3++){
                    float q3r, q3i; qvalcf(lf, cc, kset[i3], q3r, q3i);
                    float w = w3j_entryf(lo, li, lf, mset[i1], nset[i2], kset[i3], F, Fi, s_pref0, s_inv2j3);
                    if (w != 0.f){
                        re  += (q12r*q3r - q12i*q3i) * w;
                        imv += (q12r*q3i + q12i*q3r) * w;
                    }
                }
            }
        }
        sre[e] = re; sim2[e] = imv;
    }
    __syncthreads();
    if (threadIdx.x == 0){
        float nr = 0.f, ni = 0.f;
        for (int e = 0; e < n; e++){ nr += sre[e]*sre[e]; ni += sim2[e]*sim2[e]; }
        s_nr = nr; s_ni = ni;
    }
    __syncthreads();
    bool use_re = (s_nr >= s_ni);
    float inv = rsqrtf(use_re ? s_nr : s_ni);
    int base = d_CGOFF[tens];
    for (int e = threadIdx.x; e < n; e += blockDim.x)
        g_CG[base + e] = (use_re ? sre[e] : sim2[e]) * inv;
}

// ============== init: A/B tables, padded layout ==============
__global__ void k_init_ab(const float* __restrict__ W1, const float* __restrict__ b1,
                          const float* __restrict__ W2){
    int p  = blockIdx.x * 256 + threadIdx.x;
    int s0 = blockIdx.y * ABCHUNK;
    if (p >= NPATH) return;
    int pn = permute_pad(p);

    float A = 0.f, Bv = 0.f;
    for (int t = 0; t < HID; t++){
        float w = W1[t], bb = b1[t];
        int rk = g_rank[t];
        bool act = (w > 0.0f) ? (rk < s0) : ((w < 0.0f) ? (rk >= s0) : (bb > 0.0f));
        if (act){
            float w2 = W2[t*NPATH + p];
            A  = fmaf(w,  w2, A);
            Bv = fmaf(bb, w2, Bv);
        }
    }
    g_A[s0*NPAD + pn] = A;
    g_B[s0*NPAD + pn] = Bv;
    #pragma unroll
    for (int d = 1; d < ABCHUNK; d++){
        int s = s0 + d;
        if (s >= NSEG) break;
        int u  = g_sortIdx[s-1];
        float w = W1[u], bb = b1[u];
        float w2 = W2[u*NPATH + p];
        float sg = (w > 0.0f) ? 1.0f : ((w < 0.0f) ? -1.0f : 0.0f);
        A  = fmaf(sg*w,  w2, A);
        Bv = fmaf(sg*bb, w2, Bv);
        g_A[s*NPAD + pn] = A;
        g_B[s*NPAD + pn] = Bv;
    }
}

// ============== main kernel ==============
// out row (loBase + u*DA + i), col c: val = sum_k CYT[j][i][k] * coeff[v][u][k]
// u-loop dynamic (warp-uniform cf vector load), i-loop compile-time (cy in regs).
template<int DA,int NLF,int KP>
__device__ __forceinline__ void pass(const float* __restrict__ cyb,  // sCYT + CYB + j*DA*KP
                                     const float* __restrict__ cfb,  // sC + PB + v*17*KP
                                     float* __restrict__ outp,       // out + rowbase*144 + col
                                     int u0, int NU){
    float cy[DA*NLF];
    #pragma unroll
    for (int i = 0; i < DA; i++){
        if (KP == 4 && NLF == 3){
            float4 v4 = *(const float4*)(cyb + i*KP);
            cy[i*NLF+0]=v4.x; cy[i*NLF+1]=v4.y; cy[i*NLF+2]=v4.z;
        } else if (KP == 8 && NLF == 5){
            float4 v4 = *(const float4*)(cyb + i*KP);
            cy[i*NLF+0]=v4.x; cy[i*NLF+1]=v4.y; cy[i*NLF+2]=v4.z; cy[i*NLF+3]=v4.w;
            cy[i*NLF+4]=cyb[i*KP+4];
        } else {
            #pragma unroll
            for (int k = 0; k < NLF; k++) cy[i*NLF+k] = cyb[i*KP+k];
        }
    }
    for (int ug = 0; ug < NU; ug++){
        const float* cfp = cfb + (u0+ug)*KP;
        float cf[NLF];
        if (KP == 4 && NLF == 3){
            float4 v4 = *(const float4*)cfp;
            cf[0]=v4.x; cf[1]=v4.y; cf[2]=v4.z;
        } else if (KP == 8 && NLF == 5){
            float4 v4 = *(const float4*)cfp;
            cf[0]=v4.x; cf[1]=v4.y; cf[2]=v4.z; cf[3]=v4.w; cf[4]=cfp[4];
        } else {
            #pragma unroll
            for (int k = 0; k < NLF; k++) cf[k] = cfp[k];
        }
        #pragma unroll
        for (int i = 0; i < DA; i++){
            float val = 0.f;
            #pragma unroll
            for (int k = 0; k < NLF; k++) val = fmaf(cy[i*NLF+k], cf[k], val);
            __stcs(outp + (ug*DA + i)*144, val);
        }
    }
}

template<int DA,int NLF1,int KP1,int NLF2,int KP2>
__device__ __forceinline__ void warp_work(const float* __restrict__ sC,
                                          const float* __restrict__ sCYT,
                                          float* __restrict__ outz,
                                          int l, int u0, int NU, int loBase,
                                          int PB0, int PB1, int PB2,
                                          int CY0, int CY1, int CY2){
    int c16 = l & 15, h = l >> 4;
    int NU0 = (NU + 1) >> 1;
    int u0h = h ? (u0 + NU0) : u0;
    int NUh = h ? (NU - NU0) : NU0;
    float* outw = outz + (loBase + u0 *DA)*144;
    float* outh = outz + (loBase + u0h*DA)*144;

    // li0 (cols 0..15): 16 lanes x u-halves
    pass<DA,1,1>(sCYT + CY0, sC + PB0 + c16*17, outh + c16, u0h, NUh);
    // li1 full (cols 16..47)
    { int cc = l; int v = cc/3, j = cc - 3*v;
      pass<DA,NLF1,KP1>(sCYT + CY1 + j*DA*KP1, sC + PB1 + v*17*KP1, outw + 16 + cc, u0, NU); }
    // li1 split (cols 48..63)
    { int cc = 32 + c16; int v = cc/3, j = cc - 3*v;
      pass<DA,NLF1,KP1>(sCYT + CY1 + j*DA*KP1, sC + PB1 + v*17*KP1, outh + 16 + cc, u0h, NUh); }
    // li2 full (cols 64..95)
    { int cc = l; int v = cc/5, j = cc - 5*v;
      pass<DA,NLF2,KP2>(sCYT + CY2 + j*DA*KP2, sC + PB2 + v*17*KP2, outw + 64 + cc, u0, NU); }
    // li2 full (cols 96..127)
    { int cc = 32 + l; int v = cc/5, j = cc - 5*v;
      pass<DA,NLF2,KP2>(sCYT + CY2 + j*DA*KP2, sC + PB2 + v*17*KP2, outw + 64 + cc, u0, NU); }
    // li2 split (cols 128..143)
    { int cc = 64 + c16; int v = cc/5, j = cc - 5*v;
      pass<DA,NLF2,KP2>(sCYT + CY2 + j*DA*KP2, sC + PB2 + v*17*KP2, outh + 64 + cc, u0h, NUh); }
}

extern __shared__ float smem[];

__global__ __launch_bounds__(288, 4)
void k_main(const float* __restrict__ r, float* __restrict__ out){
    float* sC   = smem;             // NPAD = 6800
    float* sCYT = sC + NPAD;        // 376
    float* sY   = sCYT + NCYT;      // 32

    int z   = blockIdx.x;
    int tid = threadIdx.x;
    int w   = tid >> 5, l = tid & 31;

    float x = r[3*z+0], y = r[3*z+1], zz = r[3*z+2];
    float rad = sqrtf(x*x + y*y + zz*zz);
    bool  iszero = (rad == 0.0f);
    float inv = 1.0f / fmaxf(rad, 1e-12f);
    float ux = x*inv, uy = y*inv, uz = zz*inv;

    if (tid == 0){
        float X = ux, Y = uy, Z = uz;
        float X2 = X*X, Y2 = Y*Y, Z2 = Z*Z;
        sY[0]  = 0.28209479177387814f;
        sY[1]  = 0.4886025119029199f * Y;
        sY[2]  = 0.4886025119029199f * Z;
        sY[3]  = 0.4886025119029199f * X;
        sY[4]  = 1.0925484305920792f * X*Y;
        sY[5]  = 1.0925484305920792f * Y*Z;
        sY[6]  = 0.31539156525252005f * (3.f*Z2 - 1.f);
        sY[7]  = 1.0925484305920792f * X*Z;
        sY[8]  = 0.5462742152960396f * (X2 - Y2);
        sY[9]  = 0.5900435899266435f * Y*(3.f*X2 - Y2);
        sY[10] = 2.890611442640554f  * X*Y*Z;
        sY[11] = 0.4570457994644658f * Y*(5.f*Z2 - 1.f);
        sY[12] = 0.3731763325901154f * Z*(5.f*Z2 - 3.f);
        sY[13] = 0.4570457994644658f * X*(5.f*Z2 - 1.f);
        sY[14] = 1.445305721320277f  * (X2 - Y2)*Z;
        sY[15] = 0.5900435899266435f * X*(X2 - 3.f*Y2);
        sY[16] = 2.5033429417967046f * X*Y*(X2 - Y2);
        sY[17] = 1.7701307697799304f * Y*(3.f*X2 - Y2)*Z;
        sY[18] = 0.9461746957575601f * X*Y*(7.f*Z2 - 1.f);
        sY[19] = 0.6690465435572892f * Y*Z*(7.f*Z2 - 3.f);
        sY[20] = 0.10578554691520431f * (35.f*Z2*Z2 - 30.f*Z2 + 3.f);
        sY[21] = 0.6690465435572892f * X*Z*(7.f*Z2 - 3.f);
        sY[22] = 0.47308734787878004f * (X2 - Y2)*(7.f*Z2 - 1.f);
        sY[23] = 1.7701307697799304f * X*(X2 - 3.f*Y2)*Z;
        sY[24] = 0.6258357354491761f * (X2*X2 - 6.f*X2*Y2 + Y2*Y2);
    }
    // zero CY pad region (376 words)
    if (tid < 188){ sCYT[tid] = 0.f; sCYT[tid + 188] = 0.f; }

    bool pred = (tid < HID) && (g_T[tid] < rad);
    int seg = __syncthreads_count(pred);     // barrier: sY + zeros visible

    // coeff fill (padded layout), float4: 6800/4 = 1700
    {
        const float4* A4 = (const float4*)(g_A + (size_t)seg * NPAD);
        const float4* B4 = (const float4*)(g_B + (size_t)seg * NPAD);
        float4* sC4 = (float4*)sC;
        #pragma unroll
        for (int it = 0; it < 6; it++){
            int idx = it*288 + tid;
            if (idx < NPAD/4){
                float4 a = __ldg(&A4[idx]);
                float4 b = __ldg(&B4[idx]);
                sC4[idx] = make_float4(fmaf(rad,a.x,b.x), fmaf(rad,a.y,b.y),
                                       fmaf(rad,a.z,b.z), fmaf(rad,a.w,b.w));
            }
        }
    }

    // CY fill into padded CYT
    if (tid < 259){
        int desc = g_slotdesc[tid];
        int cgbase = desc & 0x7FF;
        int lf  = (desc >> 11) & 7;
        int lo  = (desc >> 14) & 3;
        int li  = (desc >> 16) & 3;
        int tgt = desc >> 18;
        int yoff = lf*lf, dc = 2*lf + 1;
        float v = 0.f;
        for (int m = 0; m < dc; m++)
            v = fmaf(g_CG[cgbase + m], sY[yoff + m], v);
        float lm = sqrtf((float)(2*li+1) * 12.566370614359172f);
        float num = (lo == 0) ? 48.f : ((lo == 1) ? 112.f : 144.f);
        float nrm = iszero ? (lm * 0.25f) : (lm * rsqrtf(num));
        sCYT[tgt] = v * nrm;
    }
    __syncthreads();

    float* outz = out + (size_t)z * 20736;
    if (w == 0){
        warp_work<1,1,1,1,1>(sC, sCYT, outz, l, 0, 16, 0,
                             0, 272, 544, 0, 1, 4);
    } else if (w < 4){
        int u0 = (w == 1) ? 0 : ((w == 2) ? 6 : 11);
        int NU = (w == 1) ? 6 : 5;
        warp_work<3,3,4,3,4>(sC, sCYT, outz, l, u0, NU, 16,
                             816, 1088, 2176, 9, 12, 48);
    } else {
        int wi = w - 4;
        int u0 = (wi == 0) ? 0 : (4 + 3*(wi-1));   // 0,4,7,10,13
        int NU = (wi == 0) ? 4 : 3;
        warp_work<5,3,4,5,8>(sC, sCYT, outz, l, u0, NU, 64,
                             3264, 3536, 4624, 108, 116, 176);
    }
}

extern "C" void kernel_launch(void* const* d_in, const int* in_sizes, int n_in,
                              void* d_out, int out_size){
    const float* r  = (const float*)d_in[0];
    const float* W1 = (const float*)d_in[1];
    const float* b1 = (const float*)d_in[2];
    const float* W2 = (const float*)d_in[3];
    float* out = (float*)d_out;

    static bool attr_set = false;
    int smem_bytes = (NPAD + NCYT + 32) * 4;
    if (!attr_set){
        cudaFuncSetAttribute(k_main, cudaFuncAttributeMaxDynamicSharedMemorySize, smem_bytes);
        attr_set = true;
    }

    k_init_cgsort<<<20, 128>>>(W1, b1);
    dim3 abgrid((NPATH + 255)/256, (NSEG + ABCHUNK - 1)/ABCHUNK);
    k_init_ab<<<abgrid, 256>>>(W1, b1, W2);
    k_main<<<8192, 288, smem_bytes>>>(r, out);
}